// round 14
// baseline (speedup 1.0000x reference)
#include <cuda_runtime.h>
#include <cuda_fp16.h>
#include <cstdint>

#define DD   256
#define NPIX 9216
#define EPSF 2.220446049250313e-16f

#define BM 128
#define BN 128
#define BKH 32                   // fp16 per k-stage (= 64 bytes/row)
#define NKT (DD / BKH)           // 8
#define NBM (NPIX / BM)          // 72
#define NBN (NPIX / BN)          // 72
#define NSB (NPIX / 64)          // 144 64-col sub-blocks per row
#define MARGIN 1.1e-3f           // > 2E, E = fp16 hi*hi screen error bound (~4.9e-4)

// ---------------- device scratch ----------------
__device__ __half g_A[(size_t)NPIX * DD];     // fp16(Xn) [n][256]
__device__ __half g_B[(size_t)NPIX * DD];     // fp16(Yn) [m][256]
__device__ float  g_xn[(size_t)NPIX * DD];    // normalized X [n][d] (fixup reads)
__device__ float  g_yn[(size_t)NPIX * DD];    // normalized Y [m][d]
__device__ unsigned long long g_c1[(size_t)NPIX * NSB];
__device__ __half g_c2[(size_t)NPIX * NSB];   // v2, rounded UP (conservative)
__device__ int    g_idx[NPIX];
__device__ int    g_flag[NPIX];
__device__ unsigned long long g_fix[NPIX];
__device__ int    g_flagcnt;
__device__ int    g_paircnt;
__device__ int    g_pairs[(size_t)NPIX * NBN / 8];   // (n<<8|j) worklist; ample
__device__ double g_bsum[NPIX / 32];

// ---------------- helpers ----------------
__device__ __forceinline__ uint32_t smem_u32(const void* p) {
    uint32_t a;
    asm("{ .reg .u64 t; cvta.to.shared.u64 t, %1; cvt.u32.u64 %0, t; }" : "=r"(a) : "l"(p));
    return a;
}
#define SW64(off) ((off) ^ (((off) >> 3) & 0x30))

__device__ __forceinline__ unsigned int fkey(float v) {
    unsigned int u = __float_as_uint(v);
    return (u & 0x80000000u) ? ~u : (u | 0x80000000u);
}
__device__ __forceinline__ float unfkey(unsigned int h) {
    return __uint_as_float((h & 0x80000000u) ? (h ^ 0x80000000u) : ~h);
}
__device__ __forceinline__ void cpasync16(uint32_t saddr, const void* g) {
    asm volatile("cp.async.cg.shared.global [%0], [%1], 16;" :: "r"(saddr), "l"(g));
}
#define CP_COMMIT() asm volatile("cp.async.commit_group;" ::: "memory")
#define CP_WAIT1()  asm volatile("cp.async.wait_group 1;" ::: "memory")
#define CP_WAIT0()  asm volatile("cp.async.wait_group 0;" ::: "memory")

__device__ __forceinline__ void ldmatrix_x4(uint32_t* r, uint32_t addr) {
    asm volatile("ldmatrix.sync.aligned.m8n8.x4.shared.b16 {%0,%1,%2,%3}, [%4];"
                 : "=r"(r[0]), "=r"(r[1]), "=r"(r[2]), "=r"(r[3]) : "r"(addr));
}
__device__ __forceinline__ void mma16816(float* c, const uint32_t* a, uint32_t b0, uint32_t b1) {
    asm volatile("mma.sync.aligned.m16n8k16.row.col.f32.f16.f16.f32 "
                 "{%0,%1,%2,%3}, {%4,%5,%6,%7}, {%8,%9}, {%0,%1,%2,%3};"
                 : "+f"(c[0]), "+f"(c[1]), "+f"(c[2]), "+f"(c[3])
                 : "r"(a[0]), "r"(a[1]), "r"(a[2]), "r"(a[3]), "r"(b0), "r"(b1));
}

// ---------------------------------------------------------------------------
// 1) fused: inv-norms + normalized fp16 [n][d] (both), fp32 [n][d] (both),
//    and Xf output [d][n] (X only). Resets counters.
// ---------------------------------------------------------------------------
__global__ void __launch_bounds__(256) norm_all_kernel(const float* __restrict__ X,
                                                       const float* __restrict__ Y,
                                                       float* __restrict__ xf_out) {
    __shared__ float s[256][33];     // [d][n_local], padded
    __shared__ float psum[8][32];
    __shared__ float ivs[32];
    const bool isB = (blockIdx.y != 0);
    const float* src = isB ? Y : X;
    float* dstf      = isB ? g_yn : g_xn;
    __half* dsth     = isB ? g_B : g_A;
    const int n0 = blockIdx.x * 32;
    const int tx = threadIdx.x & 31, ty = threadIdx.x >> 5;

    if (blockIdx.x == 0 && blockIdx.y == 0 && threadIdx.x == 0) {
        g_flagcnt = 0; g_paircnt = 0;
    }

    float acc = 0.f;
#pragma unroll
    for (int p = 0; p < 32; p++) {
        int d = ty * 32 + p;
        float v = src[(size_t)d * NPIX + n0 + tx];
        s[d][tx] = v;
        acc = fmaf(v, v, acc);
    }
    psum[ty][tx] = acc;
    __syncthreads();
    if (ty == 0) {
        float t = 0.f;
#pragma unroll
        for (int w = 0; w < 8; w++) t += psum[w][tx];
        ivs[tx] = 1.0f / (sqrtf(t) + EPSF);
    }
    __syncthreads();

    // transposed outputs [n][d], coalesced in d
#pragma unroll
    for (int nl = ty; nl < 32; nl += 8) {
        float iv = ivs[nl];
        size_t base = (size_t)(n0 + nl) * DD;
#pragma unroll
        for (int q = 0; q < 8; q++) {
            int d = q * 32 + tx;
            float v = s[d][nl] * iv;
            dstf[base + d] = v;
            dsth[base + d] = __float2half_rn(v);
        }
    }
    // Xf output [d][n], coalesced in n
    if (!isB) {
        float iv = ivs[tx];
#pragma unroll
        for (int p = 0; p < 32; p++) {
            int d = ty * 32 + p;
            xf_out[(size_t)d * NPIX + n0 + tx] = s[d][tx] * iv;
        }
    }
}

// ---------------------------------------------------------------------------
// 2) fp16 mma.sync GEMM (K=256, 128x128 tile, BK=32, 64B rows/SW64, occ 3)
//    + per-(row, 64-col sub-block) top-2 stored directly
//    SMEM: A stages [0,8K)+[8K,16K); B stages [16K,24K)+[24K,32K)
// ---------------------------------------------------------------------------
#define SMEM_GEMM_BYTES 32768

__global__ void __launch_bounds__(128, 3) simgemm_kernel() {
    extern __shared__ char smem[];
    const uint32_t sbase = smem_u32(smem);
    const int tid  = threadIdx.x;
    const int wid  = tid >> 5;
    const int lane = tid & 31;
    const int wm   = wid & 1;
    const int wn   = wid >> 1;
    const int m0   = blockIdx.x * BM;
    const int n0   = blockIdx.y * BN;

    float c[4][8][4];
#pragma unroll
    for (int i = 0; i < 4; i++)
#pragma unroll
        for (int j = 0; j < 8; j++)
#pragma unroll
            for (int q = 0; q < 4; q++) c[i][j][q] = 0.f;

    auto load_stage = [&](int kt) {
        const int st = kt & 1;
        const int k0 = kt * BKH;
#pragma unroll
        for (int it = 0; it < 4; it++) {
            int i = tid + it * 128;
            int r = i >> 2, cb = (i & 3) << 4;
            uint32_t sa = sbase + st * 8192 + SW64((uint32_t)(r * 64 + cb));
            const char* ga = (const char*)g_A + ((size_t)(m0 + r) * DD + k0) * 2 + cb;
            cpasync16(sa, ga);
        }
#pragma unroll
        for (int it = 0; it < 4; it++) {
            int i = tid + it * 128;
            int r = i >> 2, cb = (i & 3) << 4;
            uint32_t sa = sbase + 16384 + st * 8192 + SW64((uint32_t)(r * 64 + cb));
            const char* gb = (const char*)g_B + ((size_t)(n0 + r) * DD + k0) * 2 + cb;
            cpasync16(sa, gb);
        }
        CP_COMMIT();
    };

    load_stage(0);

    const int arow = wm * 64 + (lane & 15);
    const int aoff = ((lane >> 4) << 4);
    const int brow = wn * 64 + (lane & 7) + ((lane >> 4) << 3);
    const int boff = (((lane >> 3) & 1) << 4);

    for (int kt = 0; kt < NKT; kt++) {
        if (kt + 1 < NKT) { load_stage(kt + 1); CP_WAIT1(); }
        else              { CP_WAIT0(); }
        __syncthreads();

        const int st = kt & 1;
        const uint32_t aBase = sbase + st * 8192;
        const uint32_t bBase = sbase + 16384 + st * 8192;

#pragma unroll
        for (int kk = 0; kk < 2; kk++) {
            uint32_t af[4][4], bf[4][4];
#pragma unroll
            for (int mt = 0; mt < 4; mt++)
                ldmatrix_x4(af[mt], aBase + SW64((uint32_t)((arow + mt * 16) * 64 + kk * 32 + aoff)));
#pragma unroll
            for (int nb = 0; nb < 4; nb++)
                ldmatrix_x4(bf[nb], bBase + SW64((uint32_t)((brow + nb * 16) * 64 + kk * 32 + boff)));
#pragma unroll
            for (int mt = 0; mt < 4; mt++)
#pragma unroll
                for (int np = 0; np < 8; np++)
                    mma16816(c[mt][np], af[mt], bf[np >> 1][(np & 1) * 2], bf[np >> 1][(np & 1) * 2 + 1]);
        }
        __syncthreads();
    }

    // ---- epilogue: per-(row, warp's 64 cols) top-2, stored directly ----
#pragma unroll
    for (int mt = 0; mt < 4; mt++) {
#pragma unroll
        for (int p = 0; p < 2; p++) {
            float v1 = -1e30f, v2 = -1e30f;
            int mi = 0x7fffffff;
#pragma unroll
            for (int np = 0; np < 8; np++) {
#pragma unroll
                for (int q = 0; q < 2; q++) {
                    float v = c[mt][np][p * 2 + q];
                    int m = n0 + wn * 64 + np * 8 + (lane & 3) * 2 + q;
                    if (v > v1 || (v == v1 && m < mi)) { v2 = v1; v1 = v; mi = m; }
                    else if (v > v2) v2 = v;
                }
            }
#pragma unroll
            for (int o = 1; o <= 2; o <<= 1) {
                float ov1 = __shfl_xor_sync(0xffffffffu, v1, o);
                int   omi = __shfl_xor_sync(0xffffffffu, mi, o);
                float ov2 = __shfl_xor_sync(0xffffffffu, v2, o);
                if (ov1 > v1 || (ov1 == v1 && omi < mi)) {
                    v2 = fmaxf(v1, ov2); v1 = ov1; mi = omi;
                } else {
                    v2 = fmaxf(v2, ov1);
                }
            }
            if ((lane & 3) == 0) {
                int rloc = wm * 64 + mt * 16 + (lane >> 2) + p * 8;
                size_t slot = (size_t)(m0 + rloc) * NSB + blockIdx.y * 2 + wn;
                g_c1[slot] = ((unsigned long long)fkey(v1) << 32) |
                             (unsigned int)(~(unsigned int)mi);
                g_c2[slot] = __float2half_ru(v2);   // round UP: conservative flags
            }
        }
    }
}

// ---------------------------------------------------------------------------
// 3) merge per-row candidates (16 threads/row over 144 sub-blocks); flag
//    tight rows and emit (row, sub-block) pairs within MARGIN of v1
// ---------------------------------------------------------------------------
__global__ void merge_kernel() {
    int r = threadIdx.x >> 4, l = threadIdx.x & 15;
    int n = blockIdx.x * 16 + r;
    const unsigned long long* row1 = &g_c1[(size_t)n * NSB];
    const __half* row2 = &g_c2[(size_t)n * NSB];

    unsigned long long k1 = 0ull;
#pragma unroll 3
    for (int j = l; j < NSB; j += 16) {
        unsigned long long k = row1[j];
        if (k > k1) k1 = k;
    }
#pragma unroll
    for (int o = 1; o <= 8; o <<= 1) {
        unsigned long long ok = __shfl_xor_sync(0xffffffffu, k1, o);
        if (ok > k1) k1 = ok;
    }
    unsigned int gi = ~(unsigned int)(k1 & 0xffffffffull);
    float gv1 = unfkey((unsigned int)(k1 >> 32));
    float v2 = -1e30f;
#pragma unroll 3
    for (int j = l; j < NSB; j += 16) {
        unsigned long long k = row1[j];
        unsigned int ij = ~(unsigned int)(k & 0xffffffffull);
        float cand = (ij == gi) ? __half2float(row2[j]) : unfkey((unsigned int)(k >> 32));
        if (cand > v2) v2 = cand;
    }
#pragma unroll
    for (int o = 1; o <= 8; o <<= 1)
        v2 = fmaxf(v2, __shfl_xor_sync(0xffffffffu, v2, o));

    bool flagged = (gv1 - v2 < MARGIN);
    if (l == 0) {
        g_idx[n] = (int)gi;
        if (flagged) {
            g_fix[n] = 0ull;
            int p = atomicAdd(&g_flagcnt, 1);
            g_flag[p] = n;
        }
    }
    if (flagged) {
        float thresh = gv1 - MARGIN;
#pragma unroll 3
        for (int j = l; j < NSB; j += 16) {
            float bt1 = unfkey((unsigned int)(row1[j] >> 32));
            if (bt1 >= thresh) {
                int p = atomicAdd(&g_paircnt, 1);
                g_pairs[p] = (n << 8) | j;
            }
        }
    }
}

// ---------------------------------------------------------------------------
// 4) candidate sub-block exact fp32 fixup (64 cols per pair):
//    256 threads = 8 warps x 8 m-columns; lanes own 8-float d-slices;
//    X row read coalesced from g_xn
// ---------------------------------------------------------------------------
__global__ void __launch_bounds__(256) fixup_block_kernel() {
    const int cnt = g_paircnt;
    const int wid = threadIdx.x >> 5, lane = threadIdx.x & 31;

    for (int p = blockIdx.x; p < cnt; p += gridDim.x) {
        int pk = g_pairs[p];
        int n = pk >> 8, j = pk & 255;

        const float4* xr = (const float4*)&g_xn[(size_t)n * DD + lane * 8];
        float4 xa = xr[0], xb = xr[1];

        unsigned long long best = 0ull;
        const int m_base = j * 64 + wid * 8;
#pragma unroll
        for (int i = 0; i < 8; i += 4) {
            float s[4];
#pragma unroll
            for (int b = 0; b < 4; b++) {
                const float4* yr = (const float4*)&g_yn[(size_t)(m_base + i + b) * DD + lane * 8];
                float4 ya = yr[0], yb = yr[1];
                float t;
                t = xa.x * ya.x;
                t = fmaf(xa.y, ya.y, t);
                t = fmaf(xa.z, ya.z, t);
                t = fmaf(xa.w, ya.w, t);
                t = fmaf(xb.x, yb.x, t);
                t = fmaf(xb.y, yb.y, t);
                t = fmaf(xb.z, yb.z, t);
                t = fmaf(xb.w, yb.w, t);
                s[b] = t;
            }
#pragma unroll
            for (int off = 16; off; off >>= 1) {
#pragma unroll
                for (int b = 0; b < 4; b++)
                    s[b] += __shfl_xor_sync(0xffffffffu, s[b], off);
            }
#pragma unroll
            for (int b = 0; b < 4; b++) {
                unsigned int m = (unsigned int)(m_base + i + b);
                unsigned long long k = ((unsigned long long)fkey(s[b]) << 32) |
                                       (unsigned int)(~m);
                if (k > best) best = k;
            }
        }
        if (lane == 0) atomicMax(&g_fix[n], best);
    }
}

// ---------------------------------------------------------------------------
// 5) apply fixup results to g_idx
// ---------------------------------------------------------------------------
__global__ void fixup_apply_kernel() {
    int slot = blockIdx.x * 256 + threadIdx.x;
    if (slot < g_flagcnt) {
        int n = g_flag[slot];
        g_idx[n] = (int)(~(unsigned int)(g_fix[n] & 0xffffffffull));
    }
}

// ---------------------------------------------------------------------------
// 6) gather Y_sel via smem staging: coalesced row reads + coalesced [d][n]
//    writes + fused loss partials. 32 n's per CTA.
// ---------------------------------------------------------------------------
__global__ void __launch_bounds__(256) gather_kernel(const float* __restrict__ xf,
                                                     float* __restrict__ ysel) {
    __shared__ float t[32][257];     // [n_local][d], pad 1
    __shared__ float w[8];
    const int n0 = blockIdx.x * 32;
    const int lane = threadIdx.x & 31, ty = threadIdx.x >> 5;

    // phase 1: warp per n, coalesced row reads
#pragma unroll
    for (int nl = ty; nl < 32; nl += 8) {
        size_t base = (size_t)g_idx[n0 + nl] * DD;
#pragma unroll
        for (int k = 0; k < 8; k++)
            t[nl][lane + 32 * k] = g_yn[base + lane + 32 * k];
    }
    __syncthreads();

    // phase 2: coalesced writes in n; fused loss
    float sq = 0.f;
#pragma unroll
    for (int k = 0; k < 32; k++) {
        int d = ty * 32 + k;
        float ys = t[lane][d];
        size_t o = (size_t)d * NPIX + n0 + lane;
        float xv = xf[o];
        ysel[o] = ys;
        float dd = xv - ys;
        sq = fmaf(dd, dd, sq);
    }
#pragma unroll
    for (int off = 16; off; off >>= 1) sq += __shfl_xor_sync(0xffffffffu, sq, off);
    if (lane == 0) w[ty] = sq;
    __syncthreads();
    if (threadIdx.x == 0) {
        float s = 0.f;
#pragma unroll
        for (int k = 0; k < 8; k++) s += w[k];
        g_bsum[blockIdx.x] = (double)s;
    }
}

// ---------------------------------------------------------------------------
// 7) deterministic final loss reduction
// ---------------------------------------------------------------------------
__global__ void finalize_kernel(float* __restrict__ out) {
    __shared__ double sm[256];
    double s = 0.0;
    const int NB = NPIX / 32;
    for (int i = threadIdx.x; i < NB; i += 256) s += g_bsum[i];
    sm[threadIdx.x] = s;
    __syncthreads();
    for (int k = 128; k; k >>= 1) {
        if (threadIdx.x < k) sm[threadIdx.x] += sm[threadIdx.x + k];
        __syncthreads();
    }
    if (threadIdx.x == 0) out[0] = (float)(sm[0] / (double)(DD * NPIX));
}

// ---------------------------------------------------------------------------
extern "C" void kernel_launch(void* const* d_in, const int* in_sizes, int n_in,
                              void* d_out, int out_size) {
    const float* X = (const float*)d_in[0];
    const float* Y = (const float*)d_in[1];
    // d_in[2], d_in[3] (images) are dead inputs.
    float* out    = (float*)d_out;
    float* ysel   = out + 1;
    float* xf_out = out + 1 + DD * NPIX;

    cudaFuncSetAttribute(simgemm_kernel,
                         cudaFuncAttributeMaxDynamicSharedMemorySize, SMEM_GEMM_BYTES);

    norm_all_kernel<<<dim3(NPIX / 32, 2), 256>>>(X, Y, xf_out);
    simgemm_kernel<<<dim3(NBM, NBN), 128, SMEM_GEMM_BYTES>>>();
    merge_kernel<<<NPIX / 16, 256>>>();
    fixup_block_kernel<<<2368, 256>>>();
    fixup_apply_kernel<<<NPIX / 256, 256>>>();
    gather_kernel<<<NPIX / 32, 256>>>(xf_out, ysel);
    finalize_kernel<<<1, 256>>>(out);
}

// round 15
// speedup vs baseline: 1.0728x; 1.0728x over previous
#include <cuda_runtime.h>
#include <cuda_fp16.h>
#include <cstdint>

#define DD   256
#define NPIX 9216
#define EPSF 2.220446049250313e-16f

#define BM 128
#define BN 128
#define BKH 64                   // fp16 per k-stage (= 128 bytes/row)
#define NKT (DD / BKH)           // 4
#define NBM (NPIX / BM)          // 72
#define NBN (NPIX / BN)          // 72
#define NSB (NPIX / 64)          // 144 64-col sub-blocks per row
#define MARGIN 1.1e-3f           // > 2E, E = fp16 hi*hi screen error bound (~4.9e-4)

// ---------------- device scratch ----------------
__device__ __half g_A[(size_t)NPIX * DD];     // fp16(Xn) [n][256]
__device__ __half g_B[(size_t)NPIX * DD];     // fp16(Yn) [m][256]
__device__ float  g_xn[(size_t)NPIX * DD];    // normalized X [n][d] (fixup reads)
__device__ float  g_yn[(size_t)NPIX * DD];    // normalized Y [m][d]
__device__ unsigned long long g_c1[(size_t)NPIX * NSB];
__device__ __half g_c2[(size_t)NPIX * NSB];   // v2, rounded UP (conservative)
__device__ int    g_idx[NPIX];
__device__ int    g_flag[NPIX];
__device__ unsigned long long g_fix[NPIX];
__device__ int    g_flagcnt;
__device__ int    g_paircnt;
__device__ int    g_pairs[(size_t)NPIX * NBN / 8];   // (n<<8|j) worklist; ample
__device__ double g_bsum[NPIX / 32];

// ---------------- helpers ----------------
__device__ __forceinline__ uint32_t smem_u32(const void* p) {
    uint32_t a;
    asm("{ .reg .u64 t; cvta.to.shared.u64 t, %1; cvt.u32.u64 %0, t; }" : "=r"(a) : "l"(p));
    return a;
}
#define SW128(off) ((off) ^ (((off) >> 3) & 0x70))

__device__ __forceinline__ unsigned int fkey(float v) {
    unsigned int u = __float_as_uint(v);
    return (u & 0x80000000u) ? ~u : (u | 0x80000000u);
}
__device__ __forceinline__ float unfkey(unsigned int h) {
    return __uint_as_float((h & 0x80000000u) ? (h ^ 0x80000000u) : ~h);
}
__device__ __forceinline__ void cpasync16(uint32_t saddr, const void* g) {
    asm volatile("cp.async.cg.shared.global [%0], [%1], 16;" :: "r"(saddr), "l"(g));
}
#define CP_COMMIT() asm volatile("cp.async.commit_group;" ::: "memory")
#define CP_WAIT1()  asm volatile("cp.async.wait_group 1;" ::: "memory")
#define CP_WAIT0()  asm volatile("cp.async.wait_group 0;" ::: "memory")

__device__ __forceinline__ void ldmatrix_x4(uint32_t* r, uint32_t addr) {
    asm volatile("ldmatrix.sync.aligned.m8n8.x4.shared.b16 {%0,%1,%2,%3}, [%4];"
                 : "=r"(r[0]), "=r"(r[1]), "=r"(r[2]), "=r"(r[3]) : "r"(addr));
}
__device__ __forceinline__ void mma16816(float* c, const uint32_t* a, uint32_t b0, uint32_t b1) {
    asm volatile("mma.sync.aligned.m16n8k16.row.col.f32.f16.f16.f32 "
                 "{%0,%1,%2,%3}, {%4,%5,%6,%7}, {%8,%9}, {%0,%1,%2,%3};"
                 : "+f"(c[0]), "+f"(c[1]), "+f"(c[2]), "+f"(c[3])
                 : "r"(a[0]), "r"(a[1]), "r"(a[2]), "r"(a[3]), "r"(b0), "r"(b1));
}

// ---------------------------------------------------------------------------
// 1) fused: inv-norms + normalized fp16 [n][d] (both), fp32 [n][d] (both),
//    and Xf output [d][n] (X only). Resets counters.
// ---------------------------------------------------------------------------
__global__ void __launch_bounds__(256) norm_all_kernel(const float* __restrict__ X,
                                                       const float* __restrict__ Y,
                                                       float* __restrict__ xf_out) {
    __shared__ float s[256][33];     // [d][n_local], padded
    __shared__ float psum[8][32];
    __shared__ float ivs[32];
    const bool isB = (blockIdx.y != 0);
    const float* src = isB ? Y : X;
    float* dstf      = isB ? g_yn : g_xn;
    __half* dsth     = isB ? g_B : g_A;
    const int n0 = blockIdx.x * 32;
    const int tx = threadIdx.x & 31, ty = threadIdx.x >> 5;

    if (blockIdx.x == 0 && blockIdx.y == 0 && threadIdx.x == 0) {
        g_flagcnt = 0; g_paircnt = 0;
    }

    float acc = 0.f;
#pragma unroll
    for (int p = 0; p < 32; p++) {
        int d = ty * 32 + p;
        float v = src[(size_t)d * NPIX + n0 + tx];
        s[d][tx] = v;
        acc = fmaf(v, v, acc);
    }
    psum[ty][tx] = acc;
    __syncthreads();
    if (ty == 0) {
        float t = 0.f;
#pragma unroll
        for (int w = 0; w < 8; w++) t += psum[w][tx];
        ivs[tx] = 1.0f / (sqrtf(t) + EPSF);
    }
    __syncthreads();

    // transposed outputs [n][d], coalesced in d
#pragma unroll
    for (int nl = ty; nl < 32; nl += 8) {
        float iv = ivs[nl];
        size_t base = (size_t)(n0 + nl) * DD;
#pragma unroll
        for (int q = 0; q < 8; q++) {
            int d = q * 32 + tx;
            float v = s[d][nl] * iv;
            dstf[base + d] = v;
            dsth[base + d] = __float2half_rn(v);
        }
    }
    // Xf output [d][n], coalesced in n
    if (!isB) {
        float iv = ivs[tx];
#pragma unroll
        for (int p = 0; p < 32; p++) {
            int d = ty * 32 + p;
            xf_out[(size_t)d * NPIX + n0 + tx] = s[d][tx] * iv;
        }
    }
}

// ---------------------------------------------------------------------------
// 2) fp16 mma.sync GEMM (K=256, 128x128 tile, 4 warps of 64x64, occ 2)
//    + per-(row, 64-col sub-block) top-2 stored directly (no smem merge)
// ---------------------------------------------------------------------------
#define SMEM_GEMM_BYTES 65536

__global__ void __launch_bounds__(128, 2) simgemm_kernel() {
    extern __shared__ char smem[];
    const uint32_t sbase = smem_u32(smem);
    const int tid  = threadIdx.x;
    const int wid  = tid >> 5;
    const int lane = tid & 31;
    const int wm   = wid & 1;
    const int wn   = wid >> 1;
    const int m0   = blockIdx.x * BM;
    const int n0   = blockIdx.y * BN;

    float c[4][8][4];
#pragma unroll
    for (int i = 0; i < 4; i++)
#pragma unroll
        for (int j = 0; j < 8; j++)
#pragma unroll
            for (int q = 0; q < 4; q++) c[i][j][q] = 0.f;

    auto load_stage = [&](int kt) {
        const int st = kt & 1;
        const int k0 = kt * BKH;
#pragma unroll
        for (int it = 0; it < 8; it++) {
            int i = tid + it * 128;
            int r = i >> 3, cb = (i & 7) << 4;
            uint32_t sa = sbase + st * 16384 + SW128((uint32_t)(r * 128 + cb));
            const char* ga = (const char*)g_A + ((size_t)(m0 + r) * DD + k0) * 2 + cb;
            cpasync16(sa, ga);
        }
#pragma unroll
        for (int it = 0; it < 8; it++) {
            int i = tid + it * 128;
            int r = i >> 3, cb = (i & 7) << 4;
            uint32_t sa = sbase + 32768 + st * 16384 + SW128((uint32_t)(r * 128 + cb));
            const char* gb = (const char*)g_B + ((size_t)(n0 + r) * DD + k0) * 2 + cb;
            cpasync16(sa, gb);
        }
        CP_COMMIT();
    };

    load_stage(0);

    const int arow = wm * 64 + (lane & 15);
    const int aoff = ((lane >> 4) << 4);
    const int brow = wn * 64 + (lane & 7) + ((lane >> 4) << 3);
    const int boff = (((lane >> 3) & 1) << 4);

    for (int kt = 0; kt < NKT; kt++) {
        if (kt + 1 < NKT) { load_stage(kt + 1); CP_WAIT1(); }
        else              { CP_WAIT0(); }
        __syncthreads();

        const int st = kt & 1;
        const uint32_t aBase = sbase + st * 16384;
        const uint32_t bBase = sbase + 32768 + st * 16384;

#pragma unroll
        for (int kk = 0; kk < 4; kk++) {
            uint32_t af[4][4], bf[4][4];
#pragma unroll
            for (int mt = 0; mt < 4; mt++)
                ldmatrix_x4(af[mt], aBase + SW128((uint32_t)((arow + mt * 16) * 128 + kk * 32 + aoff)));
#pragma unroll
            for (int nb = 0; nb < 4; nb++)
                ldmatrix_x4(bf[nb], bBase + SW128((uint32_t)((brow + nb * 16) * 128 + kk * 32 + boff)));
#pragma unroll
            for (int mt = 0; mt < 4; mt++)
#pragma unroll
                for (int np = 0; np < 8; np++)
                    mma16816(c[mt][np], af[mt], bf[np >> 1][(np & 1) * 2], bf[np >> 1][(np & 1) * 2 + 1]);
        }
        __syncthreads();
    }

    // ---- epilogue: per-(row, warp's 64 cols) top-2, stored directly ----
#pragma unroll
    for (int mt = 0; mt < 4; mt++) {
#pragma unroll
        for (int p = 0; p < 2; p++) {
            float v1 = -1e30f, v2 = -1e30f;
            int mi = 0x7fffffff;
#pragma unroll
            for (int np = 0; np < 8; np++) {
#pragma unroll
                for (int q = 0; q < 2; q++) {
                    float v = c[mt][np][p * 2 + q];
                    int m = n0 + wn * 64 + np * 8 + (lane & 3) * 2 + q;
                    if (v > v1 || (v == v1 && m < mi)) { v2 = v1; v1 = v; mi = m; }
                    else if (v > v2) v2 = v;
                }
            }
#pragma unroll
            for (int o = 1; o <= 2; o <<= 1) {
                float ov1 = __shfl_xor_sync(0xffffffffu, v1, o);
                int   omi = __shfl_xor_sync(0xffffffffu, mi, o);
                float ov2 = __shfl_xor_sync(0xffffffffu, v2, o);
                if (ov1 > v1 || (ov1 == v1 && omi < mi)) {
                    v2 = fmaxf(v1, ov2); v1 = ov1; mi = omi;
                } else {
                    v2 = fmaxf(v2, ov1);
                }
            }
            if ((lane & 3) == 0) {
                int rloc = wm * 64 + mt * 16 + (lane >> 2) + p * 8;
                size_t slot = (size_t)(m0 + rloc) * NSB + blockIdx.y * 2 + wn;
                g_c1[slot] = ((unsigned long long)fkey(v1) << 32) |
                             (unsigned int)(~(unsigned int)mi);
                g_c2[slot] = __float2half_ru(v2);   // round UP: conservative flags
            }
        }
    }
}

// ---------------------------------------------------------------------------
// 3) merge per-row candidates (16 threads/row over 144 sub-blocks); flag
//    tight rows and emit (row, sub-block) pairs within MARGIN of v1
// ---------------------------------------------------------------------------
__global__ void merge_kernel() {
    int r = threadIdx.x >> 4, l = threadIdx.x & 15;
    int n = blockIdx.x * 16 + r;
    const unsigned long long* row1 = &g_c1[(size_t)n * NSB];
    const __half* row2 = &g_c2[(size_t)n * NSB];

    unsigned long long k1 = 0ull;
#pragma unroll 3
    for (int j = l; j < NSB; j += 16) {
        unsigned long long k = row1[j];
        if (k > k1) k1 = k;
    }
#pragma unroll
    for (int o = 1; o <= 8; o <<= 1) {
        unsigned long long ok = __shfl_xor_sync(0xffffffffu, k1, o);
        if (ok > k1) k1 = ok;
    }
    unsigned int gi = ~(unsigned int)(k1 & 0xffffffffull);
    float gv1 = unfkey((unsigned int)(k1 >> 32));
    float v2 = -1e30f;
#pragma unroll 3
    for (int j = l; j < NSB; j += 16) {
        unsigned long long k = row1[j];
        unsigned int ij = ~(unsigned int)(k & 0xffffffffull);
        float cand = (ij == gi) ? __half2float(row2[j]) : unfkey((unsigned int)(k >> 32));
        if (cand > v2) v2 = cand;
    }
#pragma unroll
    for (int o = 1; o <= 8; o <<= 1)
        v2 = fmaxf(v2, __shfl_xor_sync(0xffffffffu, v2, o));

    bool flagged = (gv1 - v2 < MARGIN);
    if (l == 0) {
        g_idx[n] = (int)gi;
        if (flagged) {
            g_fix[n] = 0ull;
            int p = atomicAdd(&g_flagcnt, 1);
            g_flag[p] = n;
        }
    }
    if (flagged) {
        float thresh = gv1 - MARGIN;
#pragma unroll 3
        for (int j = l; j < NSB; j += 16) {
            float bt1 = unfkey((unsigned int)(row1[j] >> 32));
            if (bt1 >= thresh) {
                int p = atomicAdd(&g_paircnt, 1);
                g_pairs[p] = (n << 8) | j;
            }
        }
    }
}

// ---------------------------------------------------------------------------
// 4) candidate sub-block exact fp32 fixup (64 cols per pair):
//    256 threads = 8 warps x 8 m-columns; lanes own 8-float d-slices;
//    X row read coalesced from g_xn
// ---------------------------------------------------------------------------
__global__ void __launch_bounds__(256) fixup_block_kernel() {
    const int cnt = g_paircnt;
    const int wid = threadIdx.x >> 5, lane = threadIdx.x & 31;

    for (int p = blockIdx.x; p < cnt; p += gridDim.x) {
        int pk = g_pairs[p];
        int n = pk >> 8, j = pk & 255;

        const float4* xr = (const float4*)&g_xn[(size_t)n * DD + lane * 8];
        float4 xa = xr[0], xb = xr[1];

        unsigned long long best = 0ull;
        const int m_base = j * 64 + wid * 8;
#pragma unroll
        for (int i = 0; i < 8; i += 4) {
            float s[4];
#pragma unroll
            for (int b = 0; b < 4; b++) {
                const float4* yr = (const float4*)&g_yn[(size_t)(m_base + i + b) * DD + lane * 8];
                float4 ya = yr[0], yb = yr[1];
                float t;
                t = xa.x * ya.x;
                t = fmaf(xa.y, ya.y, t);
                t = fmaf(xa.z, ya.z, t);
                t = fmaf(xa.w, ya.w, t);
                t = fmaf(xb.x, yb.x, t);
                t = fmaf(xb.y, yb.y, t);
                t = fmaf(xb.z, yb.z, t);
                t = fmaf(xb.w, yb.w, t);
                s[b] = t;
            }
#pragma unroll
            for (int off = 16; off; off >>= 1) {
#pragma unroll
                for (int b = 0; b < 4; b++)
                    s[b] += __shfl_xor_sync(0xffffffffu, s[b], off);
            }
#pragma unroll
            for (int b = 0; b < 4; b++) {
                unsigned int m = (unsigned int)(m_base + i + b);
                unsigned long long k = ((unsigned long long)fkey(s[b]) << 32) |
                                       (unsigned int)(~m);
                if (k > best) best = k;
            }
        }
        if (lane == 0) atomicMax(&g_fix[n], best);
    }
}

// ---------------------------------------------------------------------------
// 5) apply fixup results to g_idx
// ---------------------------------------------------------------------------
__global__ void fixup_apply_kernel() {
    int slot = blockIdx.x * 256 + threadIdx.x;
    if (slot < g_flagcnt) {
        int n = g_flag[slot];
        g_idx[n] = (int)(~(unsigned int)(g_fix[n] & 0xffffffffull));
    }
}

// ---------------------------------------------------------------------------
// 6) gather Y_sel via smem staging: coalesced row reads + coalesced [d][n]
//    writes + fused loss partials. 32 n's per CTA.
// ---------------------------------------------------------------------------
__global__ void __launch_bounds__(256) gather_kernel(const float* __restrict__ xf,
                                                     float* __restrict__ ysel) {
    __shared__ float t[32][257];     // [n_local][d], pad 1
    __shared__ float w[8];
    const int n0 = blockIdx.x * 32;
    const int lane = threadIdx.x & 31, ty = threadIdx.x >> 5;

    // phase 1: warp per n, coalesced row reads
#pragma unroll
    for (int nl = ty; nl < 32; nl += 8) {
        size_t base = (size_t)g_idx[n0 + nl] * DD;
#pragma unroll
        for (int k = 0; k < 8; k++)
            t[nl][lane + 32 * k] = g_yn[base + lane + 32 * k];
    }
    __syncthreads();

    // phase 2: coalesced writes in n; fused loss
    float sq = 0.f;
#pragma unroll
    for (int k = 0; k < 32; k++) {
        int d = ty * 32 + k;
        float ys = t[lane][d];
        size_t o = (size_t)d * NPIX + n0 + lane;
        float xv = xf[o];
        ysel[o] = ys;
        float dd = xv - ys;
        sq = fmaf(dd, dd, sq);
    }
#pragma unroll
    for (int off = 16; off; off >>= 1) sq += __shfl_xor_sync(0xffffffffu, sq, off);
    if (lane == 0) w[ty] = sq;
    __syncthreads();
    if (threadIdx.x == 0) {
        float s = 0.f;
#pragma unroll
        for (int k = 0; k < 8; k++) s += w[k];
        g_bsum[blockIdx.x] = (double)s;
    }
}

// ---------------------------------------------------------------------------
// 7) deterministic final loss reduction
// ---------------------------------------------------------------------------
__global__ void finalize_kernel(float* __restrict__ out) {
    __shared__ double sm[256];
    double s = 0.0;
    const int NB = NPIX / 32;
    for (int i = threadIdx.x; i < NB; i += 256) s += g_bsum[i];
    sm[threadIdx.x] = s;
    __syncthreads();
    for (int k = 128; k; k >>= 1) {
        if (threadIdx.x < k) sm[threadIdx.x] += sm[threadIdx.x + k];
        __syncthreads();
    }
    if (threadIdx.x == 0) out[0] = (float)(sm[0] / (double)(DD * NPIX));
}

// ---------------------------------------------------------------------------
extern "C" void kernel_launch(void* const* d_in, const int* in_sizes, int n_in,
                              void* d_out, int out_size) {
    const float* X = (const float*)d_in[0];
    const float* Y = (const float*)d_in[1];
    // d_in[2], d_in[3] (images) are dead inputs.
    float* out    = (float*)d_out;
    float* ysel   = out + 1;
    float* xf_out = out + 1 + DD * NPIX;

    cudaFuncSetAttribute(simgemm_kernel,
                         cudaFuncAttributeMaxDynamicSharedMemorySize, SMEM_GEMM_BYTES);

    norm_all_kernel<<<dim3(NPIX / 32, 2), 256>>>(X, Y, xf_out);
    simgemm_kernel<<<dim3(NBM, NBN), 128, SMEM_GEMM_BYTES>>>();
    merge_kernel<<<NPIX / 16, 256>>>();
    fixup_block_kernel<<<2368, 256>>>();
    fixup_apply_kernel<<<NPIX / 256, 256>>>();
    gather_kernel<<<NPIX / 32, 256>>>(xf_out, ysel);
    finalize_kernel<<<1, 256>>>(out);
}

// round 16
// speedup vs baseline: 1.0913x; 1.0172x over previous
#include <cuda_runtime.h>
#include <cuda_fp16.h>
#include <cstdint>

#define DD   256
#define NPIX 9216
#define EPSF 2.220446049250313e-16f

#define BM 128
#define BN 128
#define BKH 64                   // fp16 per k-stage (= 128 bytes/row)
#define NKT (DD / BKH)           // 4
#define NBM (NPIX / BM)          // 72
#define NBN (NPIX / BN)          // 72
#define NSB (NPIX / 64)          // 144 64-col sub-blocks per row
#define MARGIN 1.1e-3f           // > 2E, E = fp16 hi*hi screen error bound (~4.9e-4)

// ---------------- device scratch ----------------
__device__ __half g_A[(size_t)NPIX * DD];     // fp16(Xn) [n][256]
__device__ __half g_B[(size_t)NPIX * DD];     // fp16(Yn) [m][256]
__device__ float  g_xn[(size_t)NPIX * DD];    // normalized X [n][d] (fixup reads)
__device__ float  g_yn[(size_t)NPIX * DD];    // normalized Y [m][d]
__device__ unsigned long long g_c1[(size_t)NPIX * NSB];
__device__ __half g_c2[(size_t)NPIX * NSB];   // v2, rounded UP (conservative)
__device__ int    g_idx[NPIX];                // argmax, or -1 sentinel (flagged)
__device__ unsigned long long g_fix[NPIX];
__device__ int    g_paircnt;
__device__ int    g_pairs[(size_t)NPIX * NBN / 8];   // (n<<8|j) worklist; ample
__device__ double g_bsum[NPIX / 32];

// ---------------- helpers ----------------
__device__ __forceinline__ uint32_t smem_u32(const void* p) {
    uint32_t a;
    asm("{ .reg .u64 t; cvta.to.shared.u64 t, %1; cvt.u32.u64 %0, t; }" : "=r"(a) : "l"(p));
    return a;
}
#define SW128(off) ((off) ^ (((off) >> 3) & 0x70))

__device__ __forceinline__ unsigned int fkey(float v) {
    unsigned int u = __float_as_uint(v);
    return (u & 0x80000000u) ? ~u : (u | 0x80000000u);
}
__device__ __forceinline__ float unfkey(unsigned int h) {
    return __uint_as_float((h & 0x80000000u) ? (h ^ 0x80000000u) : ~h);
}
__device__ __forceinline__ void cpasync16(uint32_t saddr, const void* g) {
    asm volatile("cp.async.cg.shared.global [%0], [%1], 16;" :: "r"(saddr), "l"(g));
}
#define CP_COMMIT() asm volatile("cp.async.commit_group;" ::: "memory")
#define CP_WAIT1()  asm volatile("cp.async.wait_group 1;" ::: "memory")
#define CP_WAIT0()  asm volatile("cp.async.wait_group 0;" ::: "memory")

__device__ __forceinline__ void ldmatrix_x4(uint32_t* r, uint32_t addr) {
    asm volatile("ldmatrix.sync.aligned.m8n8.x4.shared.b16 {%0,%1,%2,%3}, [%4];"
                 : "=r"(r[0]), "=r"(r[1]), "=r"(r[2]), "=r"(r[3]) : "r"(addr));
}
__device__ __forceinline__ void mma16816(float* c, const uint32_t* a, uint32_t b0, uint32_t b1) {
    asm volatile("mma.sync.aligned.m16n8k16.row.col.f32.f16.f16.f32 "
                 "{%0,%1,%2,%3}, {%4,%5,%6,%7}, {%8,%9}, {%0,%1,%2,%3};"
                 : "+f"(c[0]), "+f"(c[1]), "+f"(c[2]), "+f"(c[3])
                 : "r"(a[0]), "r"(a[1]), "r"(a[2]), "r"(a[3]), "r"(b0), "r"(b1));
}

// ---------------------------------------------------------------------------
// 1) fused: inv-norms + normalized fp16 [n][d] (both), fp32 [n][d] (both),
//    and Xf output [d][n] (X only). Resets counters.
// ---------------------------------------------------------------------------
__global__ void __launch_bounds__(256) norm_all_kernel(const float* __restrict__ X,
                                                       const float* __restrict__ Y,
                                                       float* __restrict__ xf_out) {
    __shared__ float s[256][33];     // [d][n_local], padded
    __shared__ float psum[8][32];
    __shared__ float ivs[32];
    const bool isB = (blockIdx.y != 0);
    const float* src = isB ? Y : X;
    float* dstf      = isB ? g_yn : g_xn;
    __half* dsth     = isB ? g_B : g_A;
    const int n0 = blockIdx.x * 32;
    const int tx = threadIdx.x & 31, ty = threadIdx.x >> 5;

    if (blockIdx.x == 0 && blockIdx.y == 0 && threadIdx.x == 0) {
        g_paircnt = 0;
    }

    float acc = 0.f;
#pragma unroll
    for (int p = 0; p < 32; p++) {
        int d = ty * 32 + p;
        float v = src[(size_t)d * NPIX + n0 + tx];
        s[d][tx] = v;
        acc = fmaf(v, v, acc);
    }
    psum[ty][tx] = acc;
    __syncthreads();
    if (ty == 0) {
        float t = 0.f;
#pragma unroll
        for (int w = 0; w < 8; w++) t += psum[w][tx];
        ivs[tx] = 1.0f / (sqrtf(t) + EPSF);
    }
    __syncthreads();

    // transposed outputs [n][d], coalesced in d
#pragma unroll
    for (int nl = ty; nl < 32; nl += 8) {
        float iv = ivs[nl];
        size_t base = (size_t)(n0 + nl) * DD;
#pragma unroll
        for (int q = 0; q < 8; q++) {
            int d = q * 32 + tx;
            float v = s[d][nl] * iv;
            dstf[base + d] = v;
            dsth[base + d] = __float2half_rn(v);
        }
    }
    // Xf output [d][n], coalesced in n
    if (!isB) {
        float iv = ivs[tx];
#pragma unroll
        for (int p = 0; p < 32; p++) {
            int d = ty * 32 + p;
            xf_out[(size_t)d * NPIX + n0 + tx] = s[d][tx] * iv;
        }
    }
}

// ---------------------------------------------------------------------------
// 2) fp16 mma.sync GEMM (K=256, 128x128 tile, 4 warps of 64x64, occ 2)
//    + per-(row, 64-col sub-block) top-2 stored directly (no smem merge)
// ---------------------------------------------------------------------------
#define SMEM_GEMM_BYTES 65536

__global__ void __launch_bounds__(128, 2) simgemm_kernel() {
    extern __shared__ char smem[];
    const uint32_t sbase = smem_u32(smem);
    const int tid  = threadIdx.x;
    const int wid  = tid >> 5;
    const int lane = tid & 31;
    const int wm   = wid & 1;
    const int wn   = wid >> 1;
    const int m0   = blockIdx.x * BM;
    const int n0   = blockIdx.y * BN;

    float c[4][8][4];
#pragma unroll
    for (int i = 0; i < 4; i++)
#pragma unroll
        for (int j = 0; j < 8; j++)
#pragma unroll
            for (int q = 0; q < 4; q++) c[i][j][q] = 0.f;

    auto load_stage = [&](int kt) {
        const int st = kt & 1;
        const int k0 = kt * BKH;
#pragma unroll
        for (int it = 0; it < 8; it++) {
            int i = tid + it * 128;
            int r = i >> 3, cb = (i & 7) << 4;
            uint32_t sa = sbase + st * 16384 + SW128((uint32_t)(r * 128 + cb));
            const char* ga = (const char*)g_A + ((size_t)(m0 + r) * DD + k0) * 2 + cb;
            cpasync16(sa, ga);
        }
#pragma unroll
        for (int it = 0; it < 8; it++) {
            int i = tid + it * 128;
            int r = i >> 3, cb = (i & 7) << 4;
            uint32_t sa = sbase + 32768 + st * 16384 + SW128((uint32_t)(r * 128 + cb));
            const char* gb = (const char*)g_B + ((size_t)(n0 + r) * DD + k0) * 2 + cb;
            cpasync16(sa, gb);
        }
        CP_COMMIT();
    };

    load_stage(0);

    const int arow = wm * 64 + (lane & 15);
    const int aoff = ((lane >> 4) << 4);
    const int brow = wn * 64 + (lane & 7) + ((lane >> 4) << 3);
    const int boff = (((lane >> 3) & 1) << 4);

    for (int kt = 0; kt < NKT; kt++) {
        if (kt + 1 < NKT) { load_stage(kt + 1); CP_WAIT1(); }
        else              { CP_WAIT0(); }
        __syncthreads();

        const int st = kt & 1;
        const uint32_t aBase = sbase + st * 16384;
        const uint32_t bBase = sbase + 32768 + st * 16384;

#pragma unroll
        for (int kk = 0; kk < 4; kk++) {
            uint32_t af[4][4], bf[4][4];
#pragma unroll
            for (int mt = 0; mt < 4; mt++)
                ldmatrix_x4(af[mt], aBase + SW128((uint32_t)((arow + mt * 16) * 128 + kk * 32 + aoff)));
#pragma unroll
            for (int nb = 0; nb < 4; nb++)
                ldmatrix_x4(bf[nb], bBase + SW128((uint32_t)((brow + nb * 16) * 128 + kk * 32 + boff)));
#pragma unroll
            for (int mt = 0; mt < 4; mt++)
#pragma unroll
                for (int np = 0; np < 8; np++)
                    mma16816(c[mt][np], af[mt], bf[np >> 1][(np & 1) * 2], bf[np >> 1][(np & 1) * 2 + 1]);
        }
        __syncthreads();
    }

    // ---- epilogue: per-(row, warp's 64 cols) top-2, stored directly ----
#pragma unroll
    for (int mt = 0; mt < 4; mt++) {
#pragma unroll
        for (int p = 0; p < 2; p++) {
            float v1 = -1e30f, v2 = -1e30f;
            int mi = 0x7fffffff;
#pragma unroll
            for (int np = 0; np < 8; np++) {
#pragma unroll
                for (int q = 0; q < 2; q++) {
                    float v = c[mt][np][p * 2 + q];
                    int m = n0 + wn * 64 + np * 8 + (lane & 3) * 2 + q;
                    if (v > v1 || (v == v1 && m < mi)) { v2 = v1; v1 = v; mi = m; }
                    else if (v > v2) v2 = v;
                }
            }
#pragma unroll
            for (int o = 1; o <= 2; o <<= 1) {
                float ov1 = __shfl_xor_sync(0xffffffffu, v1, o);
                int   omi = __shfl_xor_sync(0xffffffffu, mi, o);
                float ov2 = __shfl_xor_sync(0xffffffffu, v2, o);
                if (ov1 > v1 || (ov1 == v1 && omi < mi)) {
                    v2 = fmaxf(v1, ov2); v1 = ov1; mi = omi;
                } else {
                    v2 = fmaxf(v2, ov1);
                }
            }
            if ((lane & 3) == 0) {
                int rloc = wm * 64 + mt * 16 + (lane >> 2) + p * 8;
                size_t slot = (size_t)(m0 + rloc) * NSB + blockIdx.y * 2 + wn;
                g_c1[slot] = ((unsigned long long)fkey(v1) << 32) |
                             (unsigned int)(~(unsigned int)mi);
                g_c2[slot] = __float2half_ru(v2);   // round UP: conservative flags
            }
        }
    }
}

// ---------------------------------------------------------------------------
// 3) merge per-row candidates: single pass with (v1, idx, v2) monoid,
//    32 threads/row over 144 sub-blocks; flag via -1 sentinel + emit pairs
// ---------------------------------------------------------------------------
__global__ void merge_kernel() {
    int r = threadIdx.x >> 5, l = threadIdx.x & 31;
    int n = blockIdx.x * 8 + r;
    const unsigned long long* row1 = &g_c1[(size_t)n * NSB];
    const __half* row2 = &g_c2[(size_t)n * NSB];

    float v1 = -1e30f, v2 = -1e30f;
    unsigned int mi = 0xffffffffu;
#pragma unroll 2
    for (int j = l; j < NSB; j += 32) {
        unsigned long long k = row1[j];
        float vj = unfkey((unsigned int)(k >> 32));
        unsigned int ij = ~(unsigned int)(k & 0xffffffffull);
        float c2j = __half2float(row2[j]);
        if (vj > v1 || (vj == v1 && ij < mi)) {
            v2 = fmaxf(v1, c2j); v1 = vj; mi = ij;
        } else {
            v2 = fmaxf(v2, vj);
        }
    }
#pragma unroll
    for (int o = 1; o <= 16; o <<= 1) {
        float ov1 = __shfl_xor_sync(0xffffffffu, v1, o);
        unsigned int omi = __shfl_xor_sync(0xffffffffu, mi, o);
        float ov2 = __shfl_xor_sync(0xffffffffu, v2, o);
        if (ov1 > v1 || (ov1 == v1 && omi < mi)) {
            v2 = fmaxf(v1, ov2); v1 = ov1; mi = omi;
        } else {
            v2 = fmaxf(v2, ov1);
        }
    }

    bool flagged = (v1 - v2 < MARGIN);
    if (l == 0) {
        if (flagged) { g_fix[n] = 0ull; g_idx[n] = -1; }
        else         { g_idx[n] = (int)mi; }
    }
    if (flagged) {
        float thresh = v1 - MARGIN;
#pragma unroll 2
        for (int j = l; j < NSB; j += 32) {
            float bt1 = unfkey((unsigned int)(row1[j] >> 32));
            if (bt1 >= thresh) {
                int p = atomicAdd(&g_paircnt, 1);
                g_pairs[p] = (n << 8) | j;
            }
        }
    }
}

// ---------------------------------------------------------------------------
// 4) candidate sub-block exact fp32 fixup (64 cols per pair):
//    256 threads = 8 warps x 8 m-columns; lanes own 8-float d-slices;
//    X row read coalesced from g_xn
// ---------------------------------------------------------------------------
__global__ void __launch_bounds__(256) fixup_block_kernel() {
    const int cnt = g_paircnt;
    const int wid = threadIdx.x >> 5, lane = threadIdx.x & 31;

    for (int p = blockIdx.x; p < cnt; p += gridDim.x) {
        int pk = g_pairs[p];
        int n = pk >> 8, j = pk & 255;

        const float4* xr = (const float4*)&g_xn[(size_t)n * DD + lane * 8];
        float4 xa = xr[0], xb = xr[1];

        unsigned long long best = 0ull;
        const int m_base = j * 64 + wid * 8;
#pragma unroll
        for (int i = 0; i < 8; i += 4) {
            float s[4];
#pragma unroll
            for (int b = 0; b < 4; b++) {
                const float4* yr = (const float4*)&g_yn[(size_t)(m_base + i + b) * DD + lane * 8];
                float4 ya = yr[0], yb = yr[1];
                float t;
                t = xa.x * ya.x;
                t = fmaf(xa.y, ya.y, t);
                t = fmaf(xa.z, ya.z, t);
                t = fmaf(xa.w, ya.w, t);
                t = fmaf(xb.x, yb.x, t);
                t = fmaf(xb.y, yb.y, t);
                t = fmaf(xb.z, yb.z, t);
                t = fmaf(xb.w, yb.w, t);
                s[b] = t;
            }
#pragma unroll
            for (int off = 16; off; off >>= 1) {
#pragma unroll
                for (int b = 0; b < 4; b++)
                    s[b] += __shfl_xor_sync(0xffffffffu, s[b], off);
            }
#pragma unroll
            for (int b = 0; b < 4; b++) {
                unsigned int m = (unsigned int)(m_base + i + b);
                unsigned long long k = ((unsigned long long)fkey(s[b]) << 32) |
                                       (unsigned int)(~m);
                if (k > best) best = k;
            }
        }
        if (lane == 0) atomicMax(&g_fix[n], best);
    }
}

// ---------------------------------------------------------------------------
// 5) gather Y_sel via smem staging (sentinel decodes g_fix inline):
//    coalesced row reads + coalesced [d][n] writes + fused loss partials
// ---------------------------------------------------------------------------
__global__ void __launch_bounds__(256) gather_kernel(const float* __restrict__ xf,
                                                     float* __restrict__ ysel) {
    __shared__ float t[32][257];     // [n_local][d], pad 1
    __shared__ float w[8];
    const int n0 = blockIdx.x * 32;
    const int lane = threadIdx.x & 31, ty = threadIdx.x >> 5;

    // phase 1: warp per n, coalesced row reads
#pragma unroll
    for (int nl = ty; nl < 32; nl += 8) {
        int idx = g_idx[n0 + nl];
        if (idx < 0)
            idx = (int)(~(unsigned int)(g_fix[n0 + nl] & 0xffffffffull));
        size_t base = (size_t)idx * DD;
#pragma unroll
        for (int k = 0; k < 8; k++)
            t[nl][lane + 32 * k] = g_yn[base + lane + 32 * k];
    }
    __syncthreads();

    // phase 2: coalesced writes in n; fused loss
    float sq = 0.f;
#pragma unroll
    for (int k = 0; k < 32; k++) {
        int d = ty * 32 + k;
        float ys = t[lane][d];
        size_t o = (size_t)d * NPIX + n0 + lane;
        float xv = xf[o];
        ysel[o] = ys;
        float dd = xv - ys;
        sq = fmaf(dd, dd, sq);
    }
#pragma unroll
    for (int off = 16; off; off >>= 1) sq += __shfl_xor_sync(0xffffffffu, sq, off);
    if (lane == 0) w[ty] = sq;
    __syncthreads();
    if (threadIdx.x == 0) {
        float s = 0.f;
#pragma unroll
        for (int k = 0; k < 8; k++) s += w[k];
        g_bsum[blockIdx.x] = (double)s;
    }
}

// ---------------------------------------------------------------------------
// 6) deterministic final loss reduction
// ---------------------------------------------------------------------------
__global__ void finalize_kernel(float* __restrict__ out) {
    __shared__ double sm[256];
    double s = 0.0;
    const int NB = NPIX / 32;
    for (int i = threadIdx.x; i < NB; i += 256) s += g_bsum[i];
    sm[threadIdx.x] = s;
    __syncthreads();
    for (int k = 128; k; k >>= 1) {
        if (threadIdx.x < k) sm[threadIdx.x] += sm[threadIdx.x + k];
        __syncthreads();
    }
    if (threadIdx.x == 0) out[0] = (float)(sm[0] / (double)(DD * NPIX));
}

// ---------------------------------------------------------------------------
extern "C" void kernel_launch(void* const* d_in, const int* in_sizes, int n_in,
                              void* d_out, int out_size) {
    const float* X = (const float*)d_in[0];
    const float* Y = (const float*)d_in[1];
    // d_in[2], d_in[3] (images) are dead inputs.
    float* out    = (float*)d_out;
    float* ysel   = out + 1;
    float* xf_out = out + 1 + DD * NPIX;

    cudaFuncSetAttribute(simgemm_kernel,
                         cudaFuncAttributeMaxDynamicSharedMemorySize, SMEM_GEMM_BYTES);

    norm_all_kernel<<<dim3(NPIX / 32, 2), 256>>>(X, Y, xf_out);
    simgemm_kernel<<<dim3(NBM, NBN), 128, SMEM_GEMM_BYTES>>>();
    merge_kernel<<<NPIX / 8, 256>>>();
    fixup_block_kernel<<<2368, 256>>>();
    gather_kernel<<<NPIX / 32, 256>>>(xf_out, ysel);
    finalize_kernel<<<1, 256>>>(out);
}

// round 17
// speedup vs baseline: 1.1384x; 1.0432x over previous
#include <cuda_runtime.h>
#include <cuda_fp16.h>
#include <cstdint>

#define DD   256
#define NPIX 9216
#define EPSF 2.220446049250313e-16f

#define BM 128
#define BN 128
#define BKH 64                   // fp16 per k-stage (= 128 bytes/row)
#define NKT (DD / BKH)           // 4
#define NBM (NPIX / BM)          // 72
#define NBN (NPIX / BN)          // 72
#define NSB (NPIX / 64)          // 144 64-col sub-blocks per row
#define MARGIN 1.1e-3f           // > 2E_typ of fp16 hi*hi screen (empirically 10x headroom)

// ---------------- device scratch ----------------
__device__ __half g_A[(size_t)NPIX * DD];     // fp16(Xn) [n][256]
__device__ __half g_B[(size_t)NPIX * DD];     // fp16(Yn) [m][256]
__device__ float  g_xn[(size_t)NPIX * DD];    // normalized X [n][d] (fixup reads)
__device__ float  g_yn[(size_t)NPIX * DD];    // normalized Y [m][d]
__device__ unsigned long long g_c1[(size_t)NPIX * NSB];
__device__ __half g_c2[(size_t)NPIX * NSB];   // v2, rounded UP (conservative)
__device__ int    g_idx[NPIX];                // argmax, or -1 sentinel (flagged)
__device__ unsigned long long g_fix[NPIX];
__device__ int    g_cntfull;
__device__ int    g_cntone;
__device__ int    g_pairs_full[(size_t)NPIX * NBN / 8];  // (n<<8|j)
__device__ int    g_pairs_one[(size_t)NPIX * NBN / 8];   // (n<<14|m)
__device__ double g_bsum[NPIX / 32];

// ---------------- helpers ----------------
__device__ __forceinline__ uint32_t smem_u32(const void* p) {
    uint32_t a;
    asm("{ .reg .u64 t; cvta.to.shared.u64 t, %1; cvt.u32.u64 %0, t; }" : "=r"(a) : "l"(p));
    return a;
}
#define SW128(off) ((off) ^ (((off) >> 3) & 0x70))

__device__ __forceinline__ unsigned int fkey(float v) {
    unsigned int u = __float_as_uint(v);
    return (u & 0x80000000u) ? ~u : (u | 0x80000000u);
}
__device__ __forceinline__ float unfkey(unsigned int h) {
    return __uint_as_float((h & 0x80000000u) ? (h ^ 0x80000000u) : ~h);
}
__device__ __forceinline__ void cpasync16(uint32_t saddr, const void* g) {
    asm volatile("cp.async.cg.shared.global [%0], [%1], 16;" :: "r"(saddr), "l"(g));
}
#define CP_COMMIT() asm volatile("cp.async.commit_group;" ::: "memory")
#define CP_WAIT1()  asm volatile("cp.async.wait_group 1;" ::: "memory")
#define CP_WAIT0()  asm volatile("cp.async.wait_group 0;" ::: "memory")

__device__ __forceinline__ void ldmatrix_x4(uint32_t* r, uint32_t addr) {
    asm volatile("ldmatrix.sync.aligned.m8n8.x4.shared.b16 {%0,%1,%2,%3}, [%4];"
                 : "=r"(r[0]), "=r"(r[1]), "=r"(r[2]), "=r"(r[3]) : "r"(addr));
}
__device__ __forceinline__ void mma16816(float* c, const uint32_t* a, uint32_t b0, uint32_t b1) {
    asm volatile("mma.sync.aligned.m16n8k16.row.col.f32.f16.f16.f32 "
                 "{%0,%1,%2,%3}, {%4,%5,%6,%7}, {%8,%9}, {%0,%1,%2,%3};"
                 : "+f"(c[0]), "+f"(c[1]), "+f"(c[2]), "+f"(c[3])
                 : "r"(a[0]), "r"(a[1]), "r"(a[2]), "r"(a[3]), "r"(b0), "r"(b1));
}

// ---------------------------------------------------------------------------
// 1) fused: inv-norms + normalized fp16 [n][d] (both), fp32 [n][d] (both),
//    and Xf output [d][n] (X only). Resets counters.
// ---------------------------------------------------------------------------
__global__ void __launch_bounds__(256) norm_all_kernel(const float* __restrict__ X,
                                                       const float* __restrict__ Y,
                                                       float* __restrict__ xf_out) {
    __shared__ float s[256][33];     // [d][n_local], padded
    __shared__ float psum[8][32];
    __shared__ float ivs[32];
    const bool isB = (blockIdx.y != 0);
    const float* src = isB ? Y : X;
    float* dstf      = isB ? g_yn : g_xn;
    __half* dsth     = isB ? g_B : g_A;
    const int n0 = blockIdx.x * 32;
    const int tx = threadIdx.x & 31, ty = threadIdx.x >> 5;

    if (blockIdx.x == 0 && blockIdx.y == 0 && threadIdx.x == 0) {
        g_cntfull = 0; g_cntone = 0;
    }

    float acc = 0.f;
#pragma unroll
    for (int p = 0; p < 32; p++) {
        int d = ty * 32 + p;
        float v = src[(size_t)d * NPIX + n0 + tx];
        s[d][tx] = v;
        acc = fmaf(v, v, acc);
    }
    psum[ty][tx] = acc;
    __syncthreads();
    if (ty == 0) {
        float t = 0.f;
#pragma unroll
        for (int w = 0; w < 8; w++) t += psum[w][tx];
        ivs[tx] = 1.0f / (sqrtf(t) + EPSF);
    }
    __syncthreads();

    // transposed outputs [n][d], coalesced in d
#pragma unroll
    for (int nl = ty; nl < 32; nl += 8) {
        float iv = ivs[nl];
        size_t base = (size_t)(n0 + nl) * DD;
#pragma unroll
        for (int q = 0; q < 8; q++) {
            int d = q * 32 + tx;
            float v = s[d][nl] * iv;
            dstf[base + d] = v;
            dsth[base + d] = __float2half_rn(v);
        }
    }
    // Xf output [d][n], coalesced in n
    if (!isB) {
        float iv = ivs[tx];
#pragma unroll
        for (int p = 0; p < 32; p++) {
            int d = ty * 32 + p;
            xf_out[(size_t)d * NPIX + n0 + tx] = s[d][tx] * iv;
        }
    }
}

// ---------------------------------------------------------------------------
// 2) fp16 mma.sync GEMM (K=256, 128x128 tile, 4 warps of 64x64, occ 2)
//    + per-(row, 64-col sub-block) top-2 stored directly (no smem merge)
// ---------------------------------------------------------------------------
#define SMEM_GEMM_BYTES 65536

__global__ void __launch_bounds__(128, 2) simgemm_kernel() {
    extern __shared__ char smem[];
    const uint32_t sbase = smem_u32(smem);
    const int tid  = threadIdx.x;
    const int wid  = tid >> 5;
    const int lane = tid & 31;
    const int wm   = wid & 1;
    const int wn   = wid >> 1;
    const int m0   = blockIdx.x * BM;
    const int n0   = blockIdx.y * BN;

    float c[4][8][4];
#pragma unroll
    for (int i = 0; i < 4; i++)
#pragma unroll
        for (int j = 0; j < 8; j++)
#pragma unroll
            for (int q = 0; q < 4; q++) c[i][j][q] = 0.f;

    auto load_stage = [&](int kt) {
        const int st = kt & 1;
        const int k0 = kt * BKH;
#pragma unroll
        for (int it = 0; it < 8; it++) {
            int i = tid + it * 128;
            int r = i >> 3, cb = (i & 7) << 4;
            uint32_t sa = sbase + st * 16384 + SW128((uint32_t)(r * 128 + cb));
            const char* ga = (const char*)g_A + ((size_t)(m0 + r) * DD + k0) * 2 + cb;
            cpasync16(sa, ga);
        }
#pragma unroll
        for (int it = 0; it < 8; it++) {
            int i = tid + it * 128;
            int r = i >> 3, cb = (i & 7) << 4;
            uint32_t sa = sbase + 32768 + st * 16384 + SW128((uint32_t)(r * 128 + cb));
            const char* gb = (const char*)g_B + ((size_t)(n0 + r) * DD + k0) * 2 + cb;
            cpasync16(sa, gb);
        }
        CP_COMMIT();
    };

    load_stage(0);

    const int arow = wm * 64 + (lane & 15);
    const int aoff = ((lane >> 4) << 4);
    const int brow = wn * 64 + (lane & 7) + ((lane >> 4) << 3);
    const int boff = (((lane >> 3) & 1) << 4);

    for (int kt = 0; kt < NKT; kt++) {
        if (kt + 1 < NKT) { load_stage(kt + 1); CP_WAIT1(); }
        else              { CP_WAIT0(); }
        __syncthreads();

        const int st = kt & 1;
        const uint32_t aBase = sbase + st * 16384;
        const uint32_t bBase = sbase + 32768 + st * 16384;

#pragma unroll
        for (int kk = 0; kk < 4; kk++) {
            uint32_t af[4][4], bf[4][4];
#pragma unroll
            for (int mt = 0; mt < 4; mt++)
                ldmatrix_x4(af[mt], aBase + SW128((uint32_t)((arow + mt * 16) * 128 + kk * 32 + aoff)));
#pragma unroll
            for (int nb = 0; nb < 4; nb++)
                ldmatrix_x4(bf[nb], bBase + SW128((uint32_t)((brow + nb * 16) * 128 + kk * 32 + boff)));
#pragma unroll
            for (int mt = 0; mt < 4; mt++)
#pragma unroll
                for (int np = 0; np < 8; np++)
                    mma16816(c[mt][np], af[mt], bf[np >> 1][(np & 1) * 2], bf[np >> 1][(np & 1) * 2 + 1]);
        }
        __syncthreads();
    }

    // ---- epilogue: per-(row, warp's 64 cols) top-2, stored directly ----
#pragma unroll
    for (int mt = 0; mt < 4; mt++) {
#pragma unroll
        for (int p = 0; p < 2; p++) {
            float v1 = -1e30f, v2 = -1e30f;
            int mi = 0x7fffffff;
#pragma unroll
            for (int np = 0; np < 8; np++) {
#pragma unroll
                for (int q = 0; q < 2; q++) {
                    float v = c[mt][np][p * 2 + q];
                    int m = n0 + wn * 64 + np * 8 + (lane & 3) * 2 + q;
                    if (v > v1 || (v == v1 && m < mi)) { v2 = v1; v1 = v; mi = m; }
                    else if (v > v2) v2 = v;
                }
            }
#pragma unroll
            for (int o = 1; o <= 2; o <<= 1) {
                float ov1 = __shfl_xor_sync(0xffffffffu, v1, o);
                int   omi = __shfl_xor_sync(0xffffffffu, mi, o);
                float ov2 = __shfl_xor_sync(0xffffffffu, v2, o);
                if (ov1 > v1 || (ov1 == v1 && omi < mi)) {
                    v2 = fmaxf(v1, ov2); v1 = ov1; mi = omi;
                } else {
                    v2 = fmaxf(v2, ov1);
                }
            }
            if ((lane & 3) == 0) {
                int rloc = wm * 64 + mt * 16 + (lane >> 2) + p * 8;
                size_t slot = (size_t)(m0 + rloc) * NSB + blockIdx.y * 2 + wn;
                g_c1[slot] = ((unsigned long long)fkey(v1) << 32) |
                             (unsigned int)(~(unsigned int)mi);
                g_c2[slot] = __float2half_ru(v2);   // round UP: conservative flags
            }
        }
    }
}

// ---------------------------------------------------------------------------
// 3) merge per-row candidates: single pass with (v1, idx, v2) monoid,
//    32 threads/row; flag via -1 sentinel; classify pairs single/full
// ---------------------------------------------------------------------------
__global__ void merge_kernel() {
    int r = threadIdx.x >> 5, l = threadIdx.x & 31;
    int n = blockIdx.x * 8 + r;
    const unsigned long long* row1 = &g_c1[(size_t)n * NSB];
    const __half* row2 = &g_c2[(size_t)n * NSB];

    float v1 = -1e30f, v2 = -1e30f;
    unsigned int mi = 0xffffffffu;
#pragma unroll 2
    for (int j = l; j < NSB; j += 32) {
        unsigned long long k = row1[j];
        float vj = unfkey((unsigned int)(k >> 32));
        unsigned int ij = ~(unsigned int)(k & 0xffffffffull);
        float c2j = __half2float(row2[j]);
        if (vj > v1 || (vj == v1 && ij < mi)) {
            v2 = fmaxf(v1, c2j); v1 = vj; mi = ij;
        } else {
            v2 = fmaxf(v2, vj);
        }
    }
#pragma unroll
    for (int o = 1; o <= 16; o <<= 1) {
        float ov1 = __shfl_xor_sync(0xffffffffu, v1, o);
        unsigned int omi = __shfl_xor_sync(0xffffffffu, mi, o);
        float ov2 = __shfl_xor_sync(0xffffffffu, v2, o);
        if (ov1 > v1 || (ov1 == v1 && omi < mi)) {
            v2 = fmaxf(v1, ov2); v1 = ov1; mi = omi;
        } else {
            v2 = fmaxf(v2, ov1);
        }
    }

    bool flagged = (v1 - v2 < MARGIN);
    if (l == 0) {
        if (flagged) { g_fix[n] = 0ull; g_idx[n] = -1; }
        else         { g_idx[n] = (int)mi; }
    }
    if (flagged) {
        float thresh = v1 - MARGIN;
#pragma unroll 2
        for (int j = l; j < NSB; j += 32) {
            unsigned long long k = row1[j];
            float bt1 = unfkey((unsigned int)(k >> 32));
            if (bt1 >= thresh) {
                // v2_j stored round-up: if below thresh, block has exactly one candidate
                if (__half2float(row2[j]) < thresh) {
                    unsigned int mj = ~(unsigned int)(k & 0xffffffffull);
                    int p = atomicAdd(&g_cntone, 1);
                    g_pairs_one[p] = (n << 14) | (int)mj;
                } else {
                    int p = atomicAdd(&g_cntfull, 1);
                    g_pairs_full[p] = (n << 8) | j;
                }
            }
        }
    }
}

// ---------------------------------------------------------------------------
// 4) exact fp32 fixup:
//    phase A: full sub-blocks (64 cols), CTA per pair (8 warps x 8 m's)
//    phase B: single-column pairs, warp per pair (one 256-MAC dot)
// ---------------------------------------------------------------------------
__global__ void __launch_bounds__(256) fixup_block_kernel() {
    const int cf = g_cntfull;
    const int co = g_cntone;
    const int wid = threadIdx.x >> 5, lane = threadIdx.x & 31;

    // ---- phase A: full blocks ----
    for (int p = blockIdx.x; p < cf; p += gridDim.x) {
        int pk = g_pairs_full[p];
        int n = pk >> 8, j = pk & 255;

        const float4* xr = (const float4*)&g_xn[(size_t)n * DD + lane * 8];
        float4 xa = xr[0], xb = xr[1];

        unsigned long long best = 0ull;
        const int m_base = j * 64 + wid * 8;
#pragma unroll
        for (int i = 0; i < 8; i += 4) {
            float s[4];
#pragma unroll
            for (int b = 0; b < 4; b++) {
                const float4* yr = (const float4*)&g_yn[(size_t)(m_base + i + b) * DD + lane * 8];
                float4 ya = yr[0], yb = yr[1];
                float t;
                t = xa.x * ya.x;
                t = fmaf(xa.y, ya.y, t);
                t = fmaf(xa.z, ya.z, t);
                t = fmaf(xa.w, ya.w, t);
                t = fmaf(xb.x, yb.x, t);
                t = fmaf(xb.y, yb.y, t);
                t = fmaf(xb.z, yb.z, t);
                t = fmaf(xb.w, yb.w, t);
                s[b] = t;
            }
#pragma unroll
            for (int off = 16; off; off >>= 1) {
#pragma unroll
                for (int b = 0; b < 4; b++)
                    s[b] += __shfl_xor_sync(0xffffffffu, s[b], off);
            }
#pragma unroll
            for (int b = 0; b < 4; b++) {
                unsigned int m = (unsigned int)(m_base + i + b);
                unsigned long long k = ((unsigned long long)fkey(s[b]) << 32) |
                                       (unsigned int)(~m);
                if (k > best) best = k;
            }
        }
        if (lane == 0) atomicMax(&g_fix[n], best);
    }

    // ---- phase B: single-column pairs, warp-granular ----
    for (int p = blockIdx.x * 8 + wid; p < co; p += gridDim.x * 8) {
        int pk = g_pairs_one[p];
        int n = pk >> 14, m = pk & 16383;

        const float4* xr = (const float4*)&g_xn[(size_t)n * DD + lane * 8];
        const float4* yr = (const float4*)&g_yn[(size_t)m * DD + lane * 8];
        float4 xa = xr[0], xb = xr[1];
        float4 ya = yr[0], yb = yr[1];
        float t;
        t = xa.x * ya.x;
        t = fmaf(xa.y, ya.y, t);
        t = fmaf(xa.z, ya.z, t);
        t = fmaf(xa.w, ya.w, t);
        t = fmaf(xb.x, yb.x, t);
        t = fmaf(xb.y, yb.y, t);
        t = fmaf(xb.z, yb.z, t);
        t = fmaf(xb.w, yb.w, t);
#pragma unroll
        for (int off = 16; off; off >>= 1)
            t += __shfl_xor_sync(0xffffffffu, t, off);
        if (lane == 0) {
            unsigned long long k = ((unsigned long long)fkey(t) << 32) |
                                   (unsigned int)(~(unsigned int)m);
            atomicMax(&g_fix[n], k);
        }
    }
}

// ---------------------------------------------------------------------------
// 5) gather Y_sel via smem staging (sentinel decodes g_fix inline):
//    coalesced row reads + coalesced [d][n] writes + fused loss partials
// ---------------------------------------------------------------------------
__global__ void __launch_bounds__(256) gather_kernel(const float* __restrict__ xf,
                                                     float* __restrict__ ysel) {
    __shared__ float t[32][257];     // [n_local][d], pad 1
    __shared__ float w[8];
    const int n0 = blockIdx.x * 32;
    const int lane = threadIdx.x & 31, ty = threadIdx.x >> 5;

    // phase 1: warp per n, coalesced row reads
#pragma unroll
    for (int nl = ty; nl < 32; nl += 8) {
        int idx = g_idx[n0 + nl];
        if (idx < 0)
            idx = (int)(~(unsigned int)(g_fix[n0 + nl] & 0xffffffffull));
        size_t base = (size_t)idx * DD;
#pragma unroll
        for (int k = 0; k < 8; k++)
            t[nl][lane + 32 * k] = g_yn[base + lane + 32 * k];
    }
    __syncthreads();

    // phase 2: coalesced writes in n; fused loss
    float sq = 0.f;
#pragma unroll
    for (int k = 0; k < 32; k++) {
        int d = ty * 32 + k;
        float ys = t[lane][d];
        size_t o = (size_t)d * NPIX + n0 + lane;
        float xv = xf[o];
        ysel[o] = ys;
        float dd = xv - ys;
        sq = fmaf(dd, dd, sq);
    }
#pragma unroll
    for (int off = 16; off; off >>= 1) sq += __shfl_xor_sync(0xffffffffu, sq, off);
    if (lane == 0) w[ty] = sq;
    __syncthreads();
    if (threadIdx.x == 0) {
        float s = 0.f;
#pragma unroll
        for (int k = 0; k < 8; k++) s += w[k];
        g_bsum[blockIdx.x] = (double)s;
    }
}

// ---------------------------------------------------------------------------
// 6) deterministic final loss reduction
// ---------------------------------------------------------------------------
__global__ void finalize_kernel(float* __restrict__ out) {
    __shared__ double sm[256];
    double s = 0.0;
    const int NB = NPIX / 32;
    for (int i = threadIdx.x; i < NB; i += 256) s += g_bsum[i];
    sm[threadIdx.x] = s;
    __syncthreads();
    for (int k = 128; k; k >>= 1) {
        if (threadIdx.x < k) sm[threadIdx.x] += sm[threadIdx.x + k];
        __syncthreads();
    }
    if (threadIdx.x == 0) out[0] = (float)(sm[0] / (double)(DD * NPIX));
}

// ---------------------------------------------------------------------------
extern "C" void kernel_launch(void* const* d_in, const int* in_sizes, int n_in,
                              void* d_out, int out_size) {
    const float* X = (const float*)d_in[0];
    const float* Y = (const float*)d_in[1];
    // d_in[2], d_in[3] (images) are dead inputs.
    float* out    = (float*)d_out;
    float* ysel   = out + 1;
    float* xf_out = out + 1 + DD * NPIX;

    cudaFuncSetAttribute(simgemm_kernel,
                         cudaFuncAttributeMaxDynamicSharedMemorySize, SMEM_GEMM_BYTES);

    norm_all_kernel<<<dim3(NPIX / 32, 2), 256>>>(X, Y, xf_out);
    simgemm_kernel<<<dim3(NBM, NBN), 128, SMEM_GEMM_BYTES>>>();
    merge_kernel<<<NPIX / 8, 256>>>();
    fixup_block_kernel<<<2368, 256>>>();
    gather_kernel<<<NPIX / 32, 256>>>(xf_out, ysel);
    finalize_kernel<<<1, 256>>>(out);
}